// round 15
// baseline (speedup 1.0000x reference)
#include <cuda_runtime.h>
#include <math_constants.h>
#include <cstdint>

// Problem dims (fixed by setup_inputs)
#define BB 32
#define TT 2048
#define DD 1024
#define SPLITS 64
#define TC (TT / SPLITS)      // 32 rows per block
#define RPI 4                 // rows per iteration
#define NTHR 256              // one float4 lane per thread

// Scratch (no cudaMalloc allowed)
__device__ float g_scores[BB * TT];
__device__ float g_part_m[BB * SPLITS];
__device__ float g_part_z[BB * SPLITS];
__device__ float g_part_c[(size_t)BB * SPLITS * DD];

// ---------------------------------------------------------------------------
// Pass 1: proven streaming loop (__ldcs evict-first on the 256MB stream).
// Triggers the dependent tail launch right after publishing partials.
// ---------------------------------------------------------------------------
__global__ __launch_bounds__(NTHR) void dpa_pass1(const float* __restrict__ q,
                                                  const float* __restrict__ v) {
    const int split = blockIdx.x;
    const int b     = blockIdx.y;
    const int tid   = threadIdx.x;
    const int lane  = tid & 31;
    const int warp  = tid >> 5;

    __shared__ float red[8][RPI];

    const float4 q4 = reinterpret_cast<const float4*>(q + (size_t)b * DD)[tid];

    float  m = -CUDART_INF_F;
    float  Z = 0.0f;
    float4 c = make_float4(0.f, 0.f, 0.f, 0.f);

    const int t0 = split * TC;
    const float* vb = v + (size_t)b * TT * DD;

    for (int it = 0; it < TC; it += RPI) {
        float4 vv[RPI];
        float  p[RPI];
#pragma unroll
        for (int r = 0; r < RPI; r++) {
            vv[r] = __ldcs(
                &reinterpret_cast<const float4*>(vb + (size_t)(t0 + it + r) * DD)[tid]);
            p[r]  = q4.x * vv[r].x + q4.y * vv[r].y + q4.z * vv[r].z + q4.w * vv[r].w;
        }
#pragma unroll
        for (int r = 0; r < RPI; r++) {
#pragma unroll
            for (int o = 16; o > 0; o >>= 1)
                p[r] += __shfl_xor_sync(0xffffffffu, p[r], o);
        }
        if (lane == 0) {
#pragma unroll
            for (int r = 0; r < RPI; r++) red[warp][r] = p[r];
        }
        __syncthreads();

        float s[RPI];
#pragma unroll
        for (int r = 0; r < RPI; r++) {
            float acc = 0.f;
#pragma unroll
            for (int w = 0; w < 8; w++) acc += red[w][r];
            s[r] = acc;
        }
        __syncthreads();  // before smem reuse next iter

        if (tid < RPI) g_scores[b * TT + t0 + it + tid] = s[tid];

        float nm = m;
#pragma unroll
        for (int r = 0; r < RPI; r++) nm = fmaxf(nm, s[r]);
        const float f = __expf(m - nm);   // 0 on first iter (m = -inf)
        Z *= f;
        c.x *= f; c.y *= f; c.z *= f; c.w *= f;
#pragma unroll
        for (int r = 0; r < RPI; r++) {
            const float e = __expf(s[r] - nm);
            Z  += e;
            c.x += e * vv[r].x;
            c.y += e * vv[r].y;
            c.z += e * vv[r].z;
            c.w += e * vv[r].w;
        }
        m = nm;
    }

    reinterpret_cast<float4*>(g_part_c + (size_t)(b * SPLITS + split) * DD)[tid] = c;
    if (tid == 0) {
        g_part_m[b * SPLITS + split] = m;
        g_part_z[b * SPLITS + split] = Z;
    }

    // All this block's writes are done — contribute to the PDL trigger.
    cudaTriggerProgrammaticLaunchCompletion();
}

// ---------------------------------------------------------------------------
// Tail, grid (10, BB), launched with PDL: blocks are resident during pass1;
// cudaGridDependencySynchronize() gates the data reads only.
//  blocks 0..7 : context (8 loads/thread, 8-way smem merge)
//  blocks 8..9 : weights
// ---------------------------------------------------------------------------
__global__ __launch_bounds__(NTHR) void dpa_tail(float* __restrict__ out) {
    const int b    = blockIdx.y;
    const int part = blockIdx.x;   // 0..9
    const int tid  = threadIdx.x;
    const int lane = tid & 31;
    const int warp = tid >> 5;

    __shared__ float  se[SPLITS];
    __shared__ float  sMv, sZv;
    __shared__ float4 sacc[8][32];

    // Address setup happens pre-dependency; data reads wait for pass1.
    const float4* pc = reinterpret_cast<const float4*>(
                           g_part_c + (size_t)b * SPLITS * DD) + part * 32 + lane;
    const int i4 = (part - 8) * NTHR + tid;

    cudaGridDependencySynchronize();

    // ---- Phase 0: issue independent data loads immediately ----
    float4 pv[8];
    float4 s4;
    if (part < 8) {
        const int sg = warp;        // split group 0..7
#pragma unroll
        for (int k = 0; k < 8; k++)   // splits j = sg + 8k — all independent
            pv[k] = __ldg(&pc[(size_t)(sg + 8 * k) * (DD / 4)]);
    } else {
        s4 = __ldg(&reinterpret_cast<const float4*>(g_scores + b * TT)[i4]);
    }

    // ---- Preamble (overlaps the loads above) ----
    if (warp == 0) {
        const float m0 = g_part_m[b * SPLITS + lane];
        const float m1 = g_part_m[b * SPLITS + lane + 32];
        float M = fmaxf(m0, m1);
#pragma unroll
        for (int o = 16; o > 0; o >>= 1)
            M = fmaxf(M, __shfl_xor_sync(0xffffffffu, M, o));
        const float e0 = __expf(m0 - M);
        const float e1 = __expf(m1 - M);
        se[lane]      = e0;
        se[lane + 32] = e1;
        float z = g_part_z[b * SPLITS + lane] * e0 +
                  g_part_z[b * SPLITS + lane + 32] * e1;
#pragma unroll
        for (int o = 16; o > 0; o >>= 1)
            z += __shfl_xor_sync(0xffffffffu, z, o);
        if (lane == 0) { sMv = M; sZv = z; }
    }
    __syncthreads();

    const float M  = sMv;
    const float iZ = 1.0f / sZv;

    if (part < 8) {
        const int di = lane;
        const int sg = warp;
        float4 acc = make_float4(0.f, 0.f, 0.f, 0.f);
#pragma unroll
        for (int k = 0; k < 8; k++) {
            const float e = se[sg + 8 * k];
            acc.x += e * pv[k].x; acc.y += e * pv[k].y;
            acc.z += e * pv[k].z; acc.w += e * pv[k].w;
        }
        sacc[sg][di] = acc;
        __syncthreads();
        if (warp == 0) {
            float4 o = sacc[0][di];
#pragma unroll
            for (int j = 1; j < 8; j++) {
                const float4 a = sacc[j][di];
                o.x += a.x; o.y += a.y; o.z += a.z; o.w += a.w;
            }
            o.x *= iZ; o.y *= iZ; o.z *= iZ; o.w *= iZ;
            reinterpret_cast<float4*>(out + (size_t)b * DD)[part * 32 + di] = o;
        }
    } else {
        float4 w;
        w.x = __expf(s4.x - M) * iZ;
        w.y = __expf(s4.y - M) * iZ;
        w.z = __expf(s4.z - M) * iZ;
        w.w = __expf(s4.w - M) * iZ;
        reinterpret_cast<float4*>(out + (size_t)BB * DD + (size_t)b * TT)[i4] = w;
    }
}

extern "C" void kernel_launch(void* const* d_in, const int* in_sizes, int n_in,
                              void* d_out, int out_size) {
    const float* q = (const float*)d_in[0];   // [32,1024]
    const float* v = (const float*)d_in[1];   // [32,2048,1024]
    float* out = (float*)d_out;               // context [32*1024] ++ weights [32*2048]

    dpa_pass1<<<dim3(SPLITS, BB), NTHR>>>(q, v);

    // Tail with programmatic dependent launch on the SAME null stream as the
    // <<<>>> launch above (explicit cudaStreamLegacy handle breaks capture).
    cudaLaunchConfig_t cfg = {};
    cfg.gridDim  = dim3(10, BB, 1);
    cfg.blockDim = dim3(NTHR, 1, 1);
    cfg.dynamicSmemBytes = 0;
    cfg.stream = 0;   // null stream — identical to the <<<>>> launch
    cudaLaunchAttribute attrs[1];
    attrs[0].id = cudaLaunchAttributeProgrammaticStreamSerialization;
    attrs[0].val.programmaticStreamSerializationAllowed = 1;
    cfg.attrs = attrs;
    cfg.numAttrs = 1;
    cudaLaunchKernelEx(&cfg, dpa_tail, out);
}

// round 16
// speedup vs baseline: 1.0238x; 1.0238x over previous
#include <cuda_runtime.h>
#include <cuda_fp16.h>
#include <math_constants.h>
#include <cstdint>

// Problem dims (fixed by setup_inputs)
#define BB 32
#define TT 2048
#define DD 1024
#define SPLITS 64
#define TC (TT / SPLITS)      // 32 rows per block
#define RPI 4                 // rows per iteration
#define NTHR 256              // one float4 lane per thread

// Scratch (no cudaMalloc allowed)
__device__ float g_scores[BB * TT];
__device__ float g_part_m[BB * SPLITS];
__device__ float g_part_z[BB * SPLITS];
__device__ __half g_part_h[(size_t)BB * SPLITS * DD];   // fp16 context partials

// ---------------------------------------------------------------------------
// Pass 1: proven streaming loop (__ldcs evict-first). Partials stored fp16.
// ---------------------------------------------------------------------------
__global__ __launch_bounds__(NTHR) void dpa_pass1(const float* __restrict__ q,
                                                  const float* __restrict__ v) {
    const int split = blockIdx.x;
    const int b     = blockIdx.y;
    const int tid   = threadIdx.x;
    const int lane  = tid & 31;
    const int warp  = tid >> 5;

    __shared__ float red[8][RPI];

    const float4 q4 = reinterpret_cast<const float4*>(q + (size_t)b * DD)[tid];

    float  m = -CUDART_INF_F;
    float  Z = 0.0f;
    float4 c = make_float4(0.f, 0.f, 0.f, 0.f);

    const int t0 = split * TC;
    const float* vb = v + (size_t)b * TT * DD;

    for (int it = 0; it < TC; it += RPI) {
        float4 vv[RPI];
        float  p[RPI];
#pragma unroll
        for (int r = 0; r < RPI; r++) {
            vv[r] = __ldcs(
                &reinterpret_cast<const float4*>(vb + (size_t)(t0 + it + r) * DD)[tid]);
            p[r]  = q4.x * vv[r].x + q4.y * vv[r].y + q4.z * vv[r].z + q4.w * vv[r].w;
        }
#pragma unroll
        for (int r = 0; r < RPI; r++) {
#pragma unroll
            for (int o = 16; o > 0; o >>= 1)
                p[r] += __shfl_xor_sync(0xffffffffu, p[r], o);
        }
        if (lane == 0) {
#pragma unroll
            for (int r = 0; r < RPI; r++) red[warp][r] = p[r];
        }
        __syncthreads();

        float s[RPI];
#pragma unroll
        for (int r = 0; r < RPI; r++) {
            float acc = 0.f;
#pragma unroll
            for (int w = 0; w < 8; w++) acc += red[w][r];
            s[r] = acc;
        }
        __syncthreads();  // before smem reuse next iter

        if (tid < RPI) g_scores[b * TT + t0 + it + tid] = s[tid];

        float nm = m;
#pragma unroll
        for (int r = 0; r < RPI; r++) nm = fmaxf(nm, s[r]);
        const float f = __expf(m - nm);   // 0 on first iter (m = -inf)
        Z *= f;
        c.x *= f; c.y *= f; c.z *= f; c.w *= f;
#pragma unroll
        for (int r = 0; r < RPI; r++) {
            const float e = __expf(s[r] - nm);
            Z  += e;
            c.x += e * vv[r].x;
            c.y += e * vv[r].y;
            c.z += e * vv[r].z;
            c.w += e * vv[r].w;
        }
        m = nm;
    }

    // Publish fp16 partial (4 halves packed in one 8B store)
    {
        __half2 h0 = __floats2half2_rn(c.x, c.y);
        __half2 h1 = __floats2half2_rn(c.z, c.w);
        uint2 u;
        u.x = *reinterpret_cast<unsigned int*>(&h0);
        u.y = *reinterpret_cast<unsigned int*>(&h1);
        reinterpret_cast<uint2*>(g_part_h + (size_t)(b * SPLITS + split) * DD)[tid] = u;
    }
    if (tid == 0) {
        g_part_m[b * SPLITS + split] = m;
        g_part_z[b * SPLITS + split] = Z;
    }
}

// ---------------------------------------------------------------------------
// Tail, grid (10, BB): loads first (overlap preamble), fp16 partials (half
// the bytes of R13).
//  blocks 0..7 : context (8x 8B loads/thread, 8-way smem merge)
//  blocks 8..9 : weights
// ---------------------------------------------------------------------------
__global__ __launch_bounds__(NTHR) void dpa_tail(float* __restrict__ out) {
    const int b    = blockIdx.y;
    const int part = blockIdx.x;   // 0..9
    const int tid  = threadIdx.x;
    const int lane = tid & 31;
    const int warp = tid >> 5;

    __shared__ float  se[SPLITS];
    __shared__ float  sMv, sZv;
    __shared__ float4 sacc[8][32];

    // ---- Phase 0: issue independent data loads immediately ----
    uint2  pv[8];
    float4 s4;
    if (part < 8) {
        const int sg = warp;        // split group 0..7
        const uint2* pc = reinterpret_cast<const uint2*>(
                              g_part_h + (size_t)b * SPLITS * DD) + part * 32 + lane;
#pragma unroll
        for (int k = 0; k < 8; k++)   // splits j = sg + 8k — all independent
            pv[k] = __ldg(&pc[(size_t)(sg + 8 * k) * (DD / 4)]);
    } else {
        const int i4 = (part - 8) * NTHR + tid;
        s4 = __ldg(&reinterpret_cast<const float4*>(g_scores + b * TT)[i4]);
    }

    // ---- Preamble (overlaps the loads above) ----
    if (warp == 0) {
        const float m0 = g_part_m[b * SPLITS + lane];
        const float m1 = g_part_m[b * SPLITS + lane + 32];
        float M = fmaxf(m0, m1);
#pragma unroll
        for (int o = 16; o > 0; o >>= 1)
            M = fmaxf(M, __shfl_xor_sync(0xffffffffu, M, o));
        const float e0 = __expf(m0 - M);
        const float e1 = __expf(m1 - M);
        se[lane]      = e0;
        se[lane + 32] = e1;
        float z = g_part_z[b * SPLITS + lane] * e0 +
                  g_part_z[b * SPLITS + lane + 32] * e1;
#pragma unroll
        for (int o = 16; o > 0; o >>= 1)
            z += __shfl_xor_sync(0xffffffffu, z, o);
        if (lane == 0) { sMv = M; sZv = z; }
    }
    __syncthreads();

    const float M  = sMv;
    const float iZ = 1.0f / sZv;

    if (part < 8) {
        const int di = lane;
        const int sg = warp;
        float4 acc = make_float4(0.f, 0.f, 0.f, 0.f);
#pragma unroll
        for (int k = 0; k < 8; k++) {
            const float e = se[sg + 8 * k];
            const __half2 h0 = *reinterpret_cast<const __half2*>(&pv[k].x);
            const __half2 h1 = *reinterpret_cast<const __half2*>(&pv[k].y);
            const float2 f0 = __half22float2(h0);
            const float2 f1 = __half22float2(h1);
            acc.x += e * f0.x; acc.y += e * f0.y;
            acc.z += e * f1.x; acc.w += e * f1.y;
        }
        sacc[sg][di] = acc;
        __syncthreads();
        if (warp == 0) {
            float4 o = sacc[0][di];
#pragma unroll
            for (int j = 1; j < 8; j++) {
                const float4 a = sacc[j][di];
                o.x += a.x; o.y += a.y; o.z += a.z; o.w += a.w;
            }
            o.x *= iZ; o.y *= iZ; o.z *= iZ; o.w *= iZ;
            reinterpret_cast<float4*>(out + (size_t)b * DD)[part * 32 + di] = o;
        }
    } else {
        const int i4 = (part - 8) * NTHR + tid;
        float4 w;
        w.x = __expf(s4.x - M) * iZ;
        w.y = __expf(s4.y - M) * iZ;
        w.z = __expf(s4.z - M) * iZ;
        w.w = __expf(s4.w - M) * iZ;
        reinterpret_cast<float4*>(out + (size_t)BB * DD + (size_t)b * TT)[i4] = w;
    }
}

extern "C" void kernel_launch(void* const* d_in, const int* in_sizes, int n_in,
                              void* d_out, int out_size) {
    const float* q = (const float*)d_in[0];   // [32,1024]
    const float* v = (const float*)d_in[1];   // [32,2048,1024]
    float* out = (float*)d_out;               // context [32*1024] ++ weights [32*2048]

    dpa_pass1<<<dim3(SPLITS, BB), NTHR>>>(q, v);
    dpa_tail<<<dim3(10, BB), NTHR>>>(out);
}